// round 12
// baseline (speedup 1.0000x reference)
#include <cuda_runtime.h>

#define NN 100000

// ---- scratch (static __device__ globals; no allocation) ----
__device__ int    g_deg[NN];       // atomic-only during hist; reset each run
__device__ float  g_dinv[NN];      // read-only after node_prep
__device__ float4 g_S[NN];         // init {sx.xyz, dinv}; scatter adds {sx,0}
__device__ float4 g_Q[NN];         // READ-ONLY during scatter: {sx.xyz, 0}
__device__ float  g_w[NN];         // atomic-only during scatter: layer-2 weights
__device__ float  g_sum16[16];     // layer-2 16-dim reduction
__device__ int    g_ctr;           // last-block counter (self-resetting)

// ---------------------------------------------------------------------------
// degree histogram over dst; vectorized int2 index loads
__global__ void k_hist(const int* __restrict__ dst, int E) {
    int i      = blockIdx.x * blockDim.x + threadIdx.x;
    int stride = gridDim.x * blockDim.x;
    int half   = E >> 1;
    const int2* dst2 = (const int2*)dst;
    for (int e = i; e < half; e += stride) {
        int2 d = __ldg(&dst2[e]);
        atomicAdd(&g_deg[d.x], 1);
        atomicAdd(&g_deg[d.y], 1);
    }
    if (i == 0 && (E & 1)) atomicAdd(&g_deg[dst[E - 1]], 1);
}

// per-node: dinv = rsqrt(deg+1);
//   Q = {sx, 0}; S = {sx, dinv} (self-loop pre-included, w carries dinv);
//   w = dinv (self-loop); reset deg; zero sum16
__global__ void k_node_prep(const float* __restrict__ x) {
    int v = blockIdx.x * blockDim.x + threadIdx.x;
    if (blockIdx.x == 0 && threadIdx.x < 16) g_sum16[threadIdx.x] = 0.f;
    if (v >= NN) return;
    float d = rsqrtf((float)(g_deg[v] + 1));
    g_deg[v]  = 0;                       // deterministic across graph replays
    g_dinv[v] = d;
    g_w[v]    = d;
    float sx0 = d * x[3 * v + 0];
    float sx1 = d * x[3 * v + 1];
    float sx2 = d * x[3 * v + 2];
    g_Q[v] = make_float4(sx0, sx1, sx2, 0.f);
    g_S[v] = make_float4(sx0, sx1, sx2, d);
}

// fused edge pass, 2 edges/thread with int2 index loads (1 idx-LDG per edge):
//   per edge: gather Q[s], gather dinv[d], red.v4 S[d] += {sx,0}, red w[s] += dinv[d]
__global__ void k_scatter(const int* __restrict__ src,
                          const int* __restrict__ dst, int E) {
    int i      = blockIdx.x * blockDim.x + threadIdx.x;
    int stride = gridDim.x * blockDim.x;
    int half   = E >> 1;
    const int2* src2 = (const int2*)src;
    const int2* dst2 = (const int2*)dst;
    for (int e = i; e < half; e += stride) {
        int2 s = __ldg(&src2[e]);
        int2 d = __ldg(&dst2[e]);
        float4 q0 = __ldg(&g_Q[s.x]);
        float4 q1 = __ldg(&g_Q[s.y]);
        float dd0 = __ldg(&g_dinv[d.x]);
        float dd1 = __ldg(&g_dinv[d.y]);
        asm volatile("red.global.add.v4.f32 [%0], {%1,%2,%3,%4};"
                     :: "l"(&g_S[d.x]), "f"(q0.x), "f"(q0.y), "f"(q0.z), "f"(q0.w)
                     : "memory");
        asm volatile("red.global.add.v4.f32 [%0], {%1,%2,%3,%4};"
                     :: "l"(&g_S[d.y]), "f"(q1.x), "f"(q1.y), "f"(q1.z), "f"(q1.w)
                     : "memory");
        asm volatile("red.global.add.f32 [%0], %1;"
                     :: "l"(&g_w[s.x]), "f"(dd0)
                     : "memory");
        asm volatile("red.global.add.f32 [%0], %1;"
                     :: "l"(&g_w[s.y]), "f"(dd1)
                     : "memory");
    }
    if (i == 0 && (E & 1)) {
        int s = src[E - 1], d = dst[E - 1];
        float4 q = __ldg(&g_Q[s]);
        float dd = __ldg(&g_dinv[d]);
        asm volatile("red.global.add.v4.f32 [%0], {%1,%2,%3,%4};"
                     :: "l"(&g_S[d]), "f"(q.x), "f"(q.y), "f"(q.z), "f"(q.w)
                     : "memory");
        asm volatile("red.global.add.f32 [%0], %1;"
                     :: "l"(&g_w[s]), "f"(dd)
                     : "memory");
    }
}

// layer-1 per-node + layer-2 accumulation + FUSED final (last-block pattern):
//   a = dinv*S.xyz;  h1 = relu(a @ W1 + b1);  sum16 += (w*dinv)*h1
//   last block: out = (sum16/N) @ W2 + b2
__global__ void k_layer1(const float* __restrict__ W1, const float* __restrict__ b1,
                         const float* __restrict__ W2, const float* __restrict__ b2,
                         float* __restrict__ out) {
    int v = blockIdx.x * blockDim.x + threadIdx.x;
    float acc[16];
    #pragma unroll
    for (int j = 0; j < 16; j++) acc[j] = 0.f;

    if (v < NN) {
        float4 S = g_S[v];               // {agg.xyz (incl. self), dinv}
        float  d = S.w;
        float  wv = g_w[v] * d;
        float a0 = d * S.x;
        float a1 = d * S.y;
        float a2 = d * S.z;
        #pragma unroll
        for (int j = 0; j < 16; j++) {
            float h = __ldg(&b1[j])
                    + a0 * __ldg(&W1[j])
                    + a1 * __ldg(&W1[16 + j])
                    + a2 * __ldg(&W1[32 + j]);
            acc[j] = wv * fmaxf(h, 0.f);
        }
    }

    // warp reduce, block reduce, one atomic per feature per block
    #pragma unroll
    for (int j = 0; j < 16; j++) {
        #pragma unroll
        for (int o = 16; o > 0; o >>= 1)
            acc[j] += __shfl_down_sync(0xffffffffu, acc[j], o);
    }
    __shared__ float sm[8][16];
    __shared__ bool  is_last;
    int lane = threadIdx.x & 31, w = threadIdx.x >> 5;
    if (lane == 0) {
        #pragma unroll
        for (int j = 0; j < 16; j++) sm[w][j] = acc[j];
    }
    __syncthreads();
    if (threadIdx.x < 16) {
        float s = 0.f;
        #pragma unroll
        for (int ww = 0; ww < 8; ww++) s += sm[ww][threadIdx.x];
        atomicAdd(&g_sum16[threadIdx.x], s);
    }
    __threadfence();
    __syncthreads();
    if (threadIdx.x == 0) {
        int old = atomicAdd(&g_ctr, 1);
        is_last = (old == (int)gridDim.x - 1);
    }
    __syncthreads();
    if (is_last) {
        if (threadIdx.x == 0) g_ctr = 0;     // reset for next replay
        __threadfence();                      // acquire: sum16 atomics visible
        if (threadIdx.x < 32) {
            float o = __ldg(&b2[threadIdx.x]);
            const float inv_n = 1.0f / (float)NN;
            #pragma unroll
            for (int k = 0; k < 16; k++)
                o += (g_sum16[k] * inv_n) * __ldg(&W2[k * 32 + threadIdx.x]);
            out[threadIdx.x] = o;
        }
    }
}

// ---------------------------------------------------------------------------
extern "C" void kernel_launch(void* const* d_in, const int* in_sizes, int n_in,
                              void* d_out, int out_size) {
    const float* x   = (const float*)d_in[0];
    const int*   ei  = (const int*)d_in[1];
    const float* W1  = (const float*)d_in[2];
    const float* b1  = (const float*)d_in[3];
    const float* W2  = (const float*)d_in[4];
    const float* b2  = (const float*)d_in[5];
    float*       out = (float*)d_out;

    int E = in_sizes[1] / 2;
    const int* src = ei;
    const int* dst = ei + E;

    int nb_nodes = (NN + 255) / 256;
    int nb_half  = ((E / 2) + 255) / 256;
    if (nb_half > 9600) nb_half = 9600;

    k_hist<<<nb_half, 256>>>(dst, E);
    k_node_prep<<<nb_nodes, 256>>>(x);
    k_scatter<<<nb_half, 256>>>(src, dst, E);
    k_layer1<<<nb_nodes, 256>>>(W1, b1, W2, b2, out);
}

// round 13
// speedup vs baseline: 1.0260x; 1.0260x over previous
#include <cuda_runtime.h>

#define NN 100000

// ---- scratch (static __device__ globals; no allocation) ----
__device__ int    g_deg[NN];       // atomic-only during hist; reset each run
__device__ float  g_dinv[NN];      // read-only after node_prep
__device__ float4 g_S[NN];         // init {sx.xyz, dinv}; scatter adds {sx,0} -> w preserved
__device__ float4 g_Q[NN];         // READ-ONLY during scatter: {sx.xyz, 0}
__device__ float  g_w[NN];         // atomic-only during scatter: layer-2 weights
__device__ float  g_sum16[16];     // layer-2 16-dim reduction

// ---------------------------------------------------------------------------
// degree histogram over dst; vectorized int2 index loads
__global__ void k_hist(const int* __restrict__ dst, int E) {
    int i      = blockIdx.x * blockDim.x + threadIdx.x;
    int stride = gridDim.x * blockDim.x;
    int half   = E >> 1;
    const int2* dst2 = (const int2*)dst;
    for (int e = i; e < half; e += stride) {
        int2 d = __ldg(&dst2[e]);
        atomicAdd(&g_deg[d.x], 1);
        atomicAdd(&g_deg[d.y], 1);
    }
    if (i == 0 && (E & 1)) atomicAdd(&g_deg[dst[E - 1]], 1);
}

// per-node: dinv = rsqrt(deg+1);
//   Q = {sx, 0} (payload; w=0 preserves S.w through the v4 red)
//   S = {sx, dinv} (self-loop pre-included; w carries dinv)
//   w = dinv (self-loop); reset deg; zero sum16
__global__ void k_node_prep(const float* __restrict__ x) {
    int v = blockIdx.x * blockDim.x + threadIdx.x;
    if (blockIdx.x == 0 && threadIdx.x < 16) g_sum16[threadIdx.x] = 0.f;
    if (v >= NN) return;
    float d = rsqrtf((float)(g_deg[v] + 1));
    g_deg[v]  = 0;                       // deterministic across graph replays
    g_dinv[v] = d;
    g_w[v]    = d;
    float sx0 = d * x[3 * v + 0];
    float sx1 = d * x[3 * v + 1];
    float sx2 = d * x[3 * v + 2];
    g_Q[v] = make_float4(sx0, sx1, sx2, 0.f);
    g_S[v] = make_float4(sx0, sx1, sx2, d);
}

// fused edge pass, 2 edges/thread, int2 index loads; 4 random wf/edge:
//   gather Q[s], gather dinv[d], red.v4 S[d] += {sx,0}, red w[s] += dinv[d]
__global__ void k_scatter(const int* __restrict__ src,
                          const int* __restrict__ dst, int E) {
    int i      = blockIdx.x * blockDim.x + threadIdx.x;
    int stride = gridDim.x * blockDim.x;
    int half   = E >> 1;
    const int2* src2 = (const int2*)src;
    const int2* dst2 = (const int2*)dst;
    for (int e = i; e < half; e += stride) {
        int2 s = __ldg(&src2[e]);
        int2 d = __ldg(&dst2[e]);
        float4 q0 = __ldg(&g_Q[s.x]);
        float4 q1 = __ldg(&g_Q[s.y]);
        float dd0 = __ldg(&g_dinv[d.x]);
        float dd1 = __ldg(&g_dinv[d.y]);
        asm volatile("red.global.add.v4.f32 [%0], {%1,%2,%3,%4};"
                     :: "l"(&g_S[d.x]), "f"(q0.x), "f"(q0.y), "f"(q0.z), "f"(q0.w)
                     : "memory");
        asm volatile("red.global.add.f32 [%0], %1;"
                     :: "l"(&g_w[s.x]), "f"(dd0)
                     : "memory");
        asm volatile("red.global.add.v4.f32 [%0], {%1,%2,%3,%4};"
                     :: "l"(&g_S[d.y]), "f"(q1.x), "f"(q1.y), "f"(q1.z), "f"(q1.w)
                     : "memory");
        asm volatile("red.global.add.f32 [%0], %1;"
                     :: "l"(&g_w[s.y]), "f"(dd1)
                     : "memory");
    }
    if (i == 0 && (E & 1)) {
        int s = src[E - 1], d = dst[E - 1];
        float4 q = __ldg(&g_Q[s]);
        float dd = __ldg(&g_dinv[d]);
        asm volatile("red.global.add.v4.f32 [%0], {%1,%2,%3,%4};"
                     :: "l"(&g_S[d]), "f"(q.x), "f"(q.y), "f"(q.z), "f"(q.w)
                     : "memory");
        asm volatile("red.global.add.f32 [%0], %1;"
                     :: "l"(&g_w[s]), "f"(dd)
                     : "memory");
    }
}

// layer-1 per-node + layer-2 accumulation; 20B/node (S + w):
//   a = dinv*S.xyz;  h1 = relu(a @ W1 + b1);  sum16 += (w*dinv)*h1
__global__ void k_layer1(const float* __restrict__ W1, const float* __restrict__ b1) {
    int v = blockIdx.x * blockDim.x + threadIdx.x;
    float acc[16];
    #pragma unroll
    for (int j = 0; j < 16; j++) acc[j] = 0.f;

    if (v < NN) {
        float4 S = g_S[v];               // {agg.xyz (incl. self), dinv}
        float  d = S.w;
        float  wv = g_w[v] * d;
        float a0 = d * S.x;
        float a1 = d * S.y;
        float a2 = d * S.z;
        #pragma unroll
        for (int j = 0; j < 16; j++) {
            float h = __ldg(&b1[j])
                    + a0 * __ldg(&W1[j])
                    + a1 * __ldg(&W1[16 + j])
                    + a2 * __ldg(&W1[32 + j]);
            acc[j] = wv * fmaxf(h, 0.f);
        }
    }

    // warp reduce, block reduce, one atomic per feature per block
    #pragma unroll
    for (int j = 0; j < 16; j++) {
        #pragma unroll
        for (int o = 16; o > 0; o >>= 1)
            acc[j] += __shfl_down_sync(0xffffffffu, acc[j], o);
    }
    __shared__ float sm[8][16];
    int lane = threadIdx.x & 31, w = threadIdx.x >> 5;
    if (lane == 0) {
        #pragma unroll
        for (int j = 0; j < 16; j++) sm[w][j] = acc[j];
    }
    __syncthreads();
    if (threadIdx.x < 16) {
        float s = 0.f;
        #pragma unroll
        for (int ww = 0; ww < 8; ww++) s += sm[ww][threadIdx.x];
        atomicAdd(&g_sum16[threadIdx.x], s);
    }
}

// final: out[j] = (sum16/N) @ W2 + b2
__global__ void k_final(const float* __restrict__ W2, const float* __restrict__ b2,
                        float* __restrict__ out) {
    int j = threadIdx.x;
    if (j >= 32) return;
    float s = __ldg(&b2[j]);
    const float inv_n = 1.0f / (float)NN;
    #pragma unroll
    for (int k = 0; k < 16; k++)
        s += (g_sum16[k] * inv_n) * __ldg(&W2[k * 32 + j]);
    out[j] = s;
}

// ---------------------------------------------------------------------------
extern "C" void kernel_launch(void* const* d_in, const int* in_sizes, int n_in,
                              void* d_out, int out_size) {
    const float* x   = (const float*)d_in[0];
    const int*   ei  = (const int*)d_in[1];
    const float* W1  = (const float*)d_in[2];
    const float* b1  = (const float*)d_in[3];
    const float* W2  = (const float*)d_in[4];
    const float* b2  = (const float*)d_in[5];
    float*       out = (float*)d_out;

    int E = in_sizes[1] / 2;
    const int* src = ei;
    const int* dst = ei + E;

    int nb_nodes = (NN + 255) / 256;
    int nb_half  = ((E / 2) + 255) / 256;
    if (nb_half > 9600) nb_half = 9600;

    k_hist<<<nb_half, 256>>>(dst, E);
    k_node_prep<<<nb_nodes, 256>>>(x);
    k_scatter<<<nb_half, 256>>>(src, dst, E);
    k_layer1<<<nb_nodes, 256>>>(W1, b1);
    k_final<<<1, 32>>>(W2, b2, out);
}